// round 14
// baseline (speedup 1.0000x reference)
#include <cuda_runtime.h>

// Kalman filter, simple-form update, column-split 16-lane layout (R11 base)
// with reduced shuffle count.
// B=4096, T=200, S=8, M=2.
// 16 lanes/batch: lane (i = row, c = col half) owns P[i][4c..4c+3].
// 2 batches per warp, 2048 warps (~3.46/SMSP).
// Deltas vs the 163.9us kernel:
//   - full F row prefetched into registers (no fo shuffles, SEL-free G loop)
//   - P' computed as own/other j-partials + ONE 4-shuffle exchange
//     (F stored in two 4-row blocks: rows0-3 [chunk0|chunk4],
//      rows4-7 [chunk4|chunk0] so both partial streams are fixed-base)
//   - HP stored as split HP0[8],HP1[8] (conflict-free own-column reads)
// All matmul LDS verified bank-disjoint: WSF=184 (==24 mod 32),
// OPU {0,36}, F bases {68,104,72,108}, HP {136,144}.

namespace {
constexpr int Bb  = 4096;
constexpr int Tt  = 200;
constexpr int WSF = 184;
constexpr unsigned FULL = 0xffffffffu;
// per-batch SMEM float offsets (16B-aligned)
constexpr int OPUL = 0;    // Pu cols 0..3, row j at +j*4
constexpr int OPUH = 36;   // Pu cols 4..7
constexpr int OFA  = 68;   // F rows 0..3: [chunk0 | chunk4], 8 f/row
constexpr int OFB  = 104;  // F rows 4..7: [chunk4 | chunk0]
constexpr int OHP0 = 136;  // HP[0][0..7]
constexpr int OHP1 = 144;  // HP[1][0..7]
constexpr int OMU  = 152;  // updated mean (8)
constexpr int OMN  = 160;  // predicted mean (8)
}

__global__ __launch_bounds__(32)
void kalman_kernel(const float* __restrict__ gy,      // [B,T,2]
                   const float* __restrict__ gF,      // [B,T,8,8]
                   const float* __restrict__ gH,      // [B,T,2,8]
                   const float* __restrict__ gQ,      // [8,8]
                   const float* __restrict__ gR,      // [2,2]
                   const float* __restrict__ gMean0,  // [B,8]
                   const float* __restrict__ gCov0,   // [8,8]
                   float* __restrict__ oMean,         // [B,T,8]
                   float* __restrict__ oCov)          // [B,T,8,8]
{
    __shared__ __align__(16) float sw[2 * WSF];
    const int lane = threadIdx.x;
    const int lb   = lane >> 4;          // batch within warp
    const int i    = lane & 7;           // state row
    const int c    = (lane >> 3) & 1;    // column half
    const int cb   = 4 * c;              // own column base
    const int b    = blockIdx.x * 2 + lb;

    float* wsp = sw + lb * WSF;
    const int opu  = c ? OPUH : OPUL;
    // F store slot for own chunk: rows0-3 in block A, rows4-7 in block B
    const int fst  = (i < 4) ? (OFA + i * 8 + (c ? 4 : 0))
                             : (OFB + (i - 4) * 8 + (c ? 0 : 4));
    // P' partial read bases: own k rows w/ own j-chunk; other k rows w/ own j-chunk
    const int bOwn = c ? OFB : OFA;
    const int bOth = (c ? OFA : OFB) + 4;

    const float R00 = gR[0], R01 = gR[1], R10 = gR[2], R11 = gR[3];
    float Qr[4];
#pragma unroll
    for (int m = 0; m < 4; ++m) Qr[m] = gQ[i * 8 + cb + m];

    float* omb = oMean + (size_t)b * Tt * 8;
    float* ocb = oCov  + (size_t)b * Tt * 64;

    // ---- init: own quarter-row of P; t=0 outputs ----
    float pr[4];
    {
        const float4 p0 = *(const float4*)(gCov0 + i * 8 + cb);
        pr[0]=p0.x; pr[1]=p0.y; pr[2]=p0.z; pr[3]=p0.w;
        *(float4*)(ocb + i * 8 + cb) = p0;
    }
    if (c == 0) {
        const float m0 = gMean0[b * 8 + i];
        wsp[OMN + i] = m0;
        omb[i]       = m0;
    }

    const float* Fb = gF + (size_t)b * Tt * 64;
    const float* Hb = gH + (size_t)b * Tt * 16;
    const float* yb = gy + (size_t)b * Tt * 2;

    // ---- prefetch step 0: FULL F row + own H quarters ----
    float4 f0n = *(const float4*)(Fb + i * 8);       // F[i][0..3]
    float4 f1n = *(const float4*)(Fb + i * 8 + 4);   // F[i][4..7]
    float4 hAn = *(const float4*)(Hb + cb);          // H[0][cb..cb+3]
    float4 hCn = *(const float4*)(Hb + 8 + cb);      // H[1][cb..cb+3]
    float2 yvn = *(const float2*)(yb);

    __syncwarp();

    for (int t = 0; t < Tt - 1; ++t) {
        const float f0[4]  = {f0n.x, f0n.y, f0n.z, f0n.w};
        const float f1[4]  = {f1n.x, f1n.y, f1n.z, f1n.w};
        const float hao[4] = {hAn.x, hAn.y, hAn.z, hAn.w};
        const float hco[4] = {hCn.x, hCn.y, hCn.z, hCn.w};
        const float y0 = yvn.x, y1 = yvn.y;

        // prefetch next step
        {
            const float* Fn = Fb + (size_t)(t + 1) * 64;
            f0n = *(const float4*)(Fn + i * 8);
            f1n = *(const float4*)(Fn + i * 8 + 4);
            const float* Hn = Hb + (size_t)(t + 1) * 16;
            hAn = *(const float4*)(Hn + cb);
            hCn = *(const float4*)(Hn + 8 + cb);
            yvn = *(const float2*)(yb + (size_t)(t + 1) * 2);
        }

        // ---- phase 1 ----
        // store own F chunk (c=0 -> chunk0 = f0, c=1 -> chunk4 = f1)
        {
            const float4 fsv = c ? make_float4(f1[0], f1[1], f1[2], f1[3])
                                 : make_float4(f0[0], f0[1], f0[2], f0[3]);
            *(float4*)(wsp + fst) = fsv;
        }
        // HP column i: partial over own cols (P symmetric) + xor reduce
        float hp0 = 0.f, hp1 = 0.f;
#pragma unroll
        for (int m = 0; m < 4; ++m) {
            hp0 += hao[m] * pr[m];
            hp1 += hco[m] * pr[m];
        }
        hp0 += __shfl_xor_sync(FULL, hp0, 8);
        hp1 += __shfl_xor_sync(FULL, hp1, 8);
        if (c == 0) {
            wsp[OHP0 + i] = hp0;
            wsp[OHP1 + i] = hp1;
        }
        // residual partials (prev-step mean, synced)
        float r0, r1;
        {
            const float4 mo = *(const float4*)(wsp + OMN + cb);
            float r0p = hao[0]*mo.x + hao[1]*mo.y + hao[2]*mo.z + hao[3]*mo.w;
            float r1p = hco[0]*mo.x + hco[1]*mo.y + hco[2]*mo.z + hco[3]*mo.w;
            r0 = y0 - (r0p + __shfl_xor_sync(FULL, r0p, 8));
            r1 = y1 - (r1p + __shfl_xor_sync(FULL, r1p, 8));
        }
        __syncwarp();  // sync A: sF, sHP visible

        // ---- phase 2: Smat, gain, P_u quarter-row, mean_u ----
        float HP0o[4], HP1o[4];
        {
            const float4 u0 = *(const float4*)(wsp + OHP0 + cb);
            const float4 u1 = *(const float4*)(wsp + OHP1 + cb);
            HP0o[0]=u0.x; HP0o[1]=u0.y; HP0o[2]=u0.z; HP0o[3]=u0.w;
            HP1o[0]=u1.x; HP1o[1]=u1.y; HP1o[2]=u1.z; HP1o[3]=u1.w;
        }
        float s00p = 0.f, s01p = 0.f, s10p = 0.f, s11p = 0.f;
#pragma unroll
        for (int m = 0; m < 4; ++m) {
            s00p += HP0o[m] * hao[m];
            s01p += HP0o[m] * hco[m];
            s10p += HP1o[m] * hao[m];
            s11p += HP1o[m] * hco[m];
        }
        const float s00 = R00 + s00p + __shfl_xor_sync(FULL, s00p, 8);
        const float s01 = R01 + s01p + __shfl_xor_sync(FULL, s01p, 8);
        const float s10 = R10 + s10p + __shfl_xor_sync(FULL, s10p, 8);
        const float s11 = R11 + s11p + __shfl_xor_sync(FULL, s11p, 8);
        const float inv = 1.0f / (s00 * s11 - s01 * s10);
        const float w0i = inv * ( s11 * hp0 - s01 * hp1);
        const float w1i = inv * (-s10 * hp0 + s00 * hp1);

        // P_u quarter-row
        float pu[4];
#pragma unroll
        for (int m = 0; m < 4; ++m)
            pu[m] = pr[m] - w0i * HP0o[m] - w1i * HP1o[m];
        *(float4*)(wsp + opu + i * 4) = make_float4(pu[0], pu[1], pu[2], pu[3]);

        if (c == 0)
            wsp[OMU + i] = wsp[OMN + i] + w0i * r0 + w1i * r1;
        __syncwarp();  // sync B: sPU, sMU visible; sMean reads done

        // ---- phase 3: predict ----
        // G[i][own cols] = sum_{j=0..7} F[i][j] * Pu[j][own cols]
        float g0 = 0.f, g1 = 0.f, g2 = 0.f, g3 = 0.f;
#pragma unroll
        for (int m = 0; m < 4; ++m) {
            const float4 pj = *(const float4*)(wsp + opu + m * 4);
            g0 += f0[m] * pj.x; g1 += f0[m] * pj.y;
            g2 += f0[m] * pj.z; g3 += f0[m] * pj.w;
        }
#pragma unroll
        for (int m = 0; m < 4; ++m) {
            const float4 pj = *(const float4*)(wsp + opu + (4 + m) * 4);
            g0 += f1[m] * pj.x; g1 += f1[m] * pj.y;
            g2 += f1[m] * pj.z; g3 += f1[m] * pj.w;
        }

        // P' partials: own-j-chunk contributions for own k and other k rows
        float pOwn[4], pOth[4];
#pragma unroll
        for (int kk = 0; kk < 4; ++kk) {
            const float4 qo = *(const float4*)(wsp + bOwn + kk * 8);
            pOwn[kk] = g0*qo.x + g1*qo.y + g2*qo.z + g3*qo.w;
        }
#pragma unroll
        for (int kk = 0; kk < 4; ++kk) {
            const float4 qt = *(const float4*)(wsp + bOth + kk * 8);
            pOth[kk] = g0*qt.x + g1*qt.y + g2*qt.z + g3*qt.w;
        }
        // partner's complementary partial for my own k rows
        float pn[4];
#pragma unroll
        for (int kk = 0; kk < 4; ++kk) {
            const float recv = __shfl_xor_sync(FULL, pOth[kk], 8);
            pn[kk] = Qr[kk] + pOwn[kk] + recv;
        }
#pragma unroll
        for (int m = 0; m < 4; ++m) pr[m] = pn[m];

        *(float4*)(ocb + (size_t)(t + 1) * 64 + i * 8 + cb) =
            make_float4(pn[0], pn[1], pn[2], pn[3]);

        // mean predict: full dot off registers (mu from SMEM)
        {
            const float4 u0 = *(const float4*)(wsp + OMU);
            const float4 u1 = *(const float4*)(wsp + OMU + 4);
            const float mp =
                  f0[0]*u0.x + f0[1]*u0.y + f0[2]*u0.z + f0[3]*u0.w
                + f1[0]*u1.x + f1[1]*u1.y + f1[2]*u1.z + f1[3]*u1.w;
            if (c == 0) {
                wsp[OMN + i] = mp;  // old-OMN reads ended before sync B
                omb[(size_t)(t + 1) * 8 + i] = mp;
            }
        }
        __syncwarp();  // sync C: phase-3 reads done; sMean visible next iter
    }
}

extern "C" void kernel_launch(void* const* d_in, const int* in_sizes, int n_in,
                              void* d_out, int out_size)
{
    // metadata order: y, F, H, Q, R, init_mean, init_cov, n_step
    const float* gy     = (const float*)d_in[0];
    const float* gF     = (const float*)d_in[1];
    const float* gH     = (const float*)d_in[2];
    const float* gQ     = (const float*)d_in[3];
    const float* gR     = (const float*)d_in[4];
    const float* gMean0 = (const float*)d_in[5];
    const float* gCov0  = (const float*)d_in[6];
    (void)in_sizes; (void)n_in;

    float* oMean = (float*)d_out;                          // [B,T,8]
    float* oCov  = (float*)d_out + (size_t)Bb * Tt * 8;    // [B,T,8,8]
    (void)out_size;

    kalman_kernel<<<Bb / 2, 32>>>(gy, gF, gH, gQ, gR, gMean0, gCov0,
                                  oMean, oCov);
}

// round 15
// speedup vs baseline: 1.6638x; 1.6638x over previous
#include <cuda_runtime.h>

// Kalman filter, simple-form update, select-free column-split layout
// (exact 163.9us round-10 kernel) + double-buffered workspace so the
// step-boundary syncwarp is eliminated (3 -> 2 syncs per step).
// B=4096, T=200, S=8, M=2.
// 16 lanes/batch: lane (i = row, c = column half) owns P[i][4c..4c+3].
// 2 batches per 32-thread warp, 2048 warps (~3.46/SMSP).
// Parity buffers at +0 / +416 floats (batch distance stays 208 == 16 mod 32,
// preserving the verified conflict-free bank patterns). sMean is a single
// parity-free copy: written early in phase 3(t), read in phase 2(t+1),
// ordered by sync A(t+1). WAR on sPU/sF/sHP/sMU is two barriers deep.

namespace {
constexpr int Bb  = 4096;
constexpr int Tt  = 200;
constexpr int WSF = 208;   // per-batch workspace stride in floats
constexpr int PSTRIDE = 2 * WSF;   // parity stride (416)
constexpr int OMEAN   = 4 * WSF;   // sMean region base (832)
constexpr unsigned FULL = 0xffffffffu;
}

__global__ __launch_bounds__(32)
void kalman_kernel(const float* __restrict__ gy,      // [B,T,2]
                   const float* __restrict__ gF,      // [B,T,8,8]
                   const float* __restrict__ gH,      // [B,T,2,8]
                   const float* __restrict__ gQ,      // [8,8]
                   const float* __restrict__ gR,      // [2,2]
                   const float* __restrict__ gMean0,  // [B,8]
                   const float* __restrict__ gCov0,   // [8,8]
                   float* __restrict__ oMean,         // [B,T,8]
                   float* __restrict__ oCov)          // [B,T,8,8]
{
    __shared__ __align__(16) float sw[4 * WSF + 32];
    const int lane = threadIdx.x;
    const int lb   = lane >> 4;          // batch within warp
    const int i    = lane & 7;           // state row
    const int c    = (lane >> 3) & 1;    // column half
    const int cb   = 4 * c;              // own column base
    const int ob   = 4 - cb;             // other column base
    const int b    = blockIdx.x * 2 + lb;

    float* swb  = sw + lb * WSF;         // parity-0 workspace base
    float* sMn  = sw + OMEAN + lb * 16;  // parity-free predicted mean (8 used)

    const float R00 = gR[0], R01 = gR[1], R10 = gR[2], R11 = gR[3];
    float Qr[4];
#pragma unroll
    for (int m = 0; m < 4; ++m) Qr[m] = gQ[i * 8 + cb + m];

    float* omb = oMean + (size_t)b * Tt * 8;
    float* ocb = oCov  + (size_t)b * Tt * 64;

    // ---- init: own quarter-row of P; t=0 outputs ----
    float pr[4];
    {
        const float4 p0 = *(const float4*)(gCov0 + i * 8 + cb);
        pr[0]=p0.x; pr[1]=p0.y; pr[2]=p0.z; pr[3]=p0.w;
        *(float4*)(ocb + i * 8 + cb) = p0;
    }
    if (c == 0) {
        const float m0 = gMean0[b * 8 + i];
        sMn[i]  = m0;
        omb[i]  = m0;
    }

    const float* Fb = gF + (size_t)b * Tt * 64;
    const float* Hb = gH + (size_t)b * Tt * 16;
    const float* yb = gy + (size_t)b * Tt * 2;

    // ---- prefetch step 0: own quarters only ----
    float4 fh = *(const float4*)(Fb + i * 8 + cb);   // F[i][cb..cb+3]
    float4 hA = *(const float4*)(Hb + cb);           // H[0][cb..cb+3]
    float4 hC = *(const float4*)(Hb + 8 + cb);       // H[1][cb..cb+3]
    float2 yv = *(const float2*)(yb);

    __syncwarp();

    for (int t = 0; t < Tt - 1; ++t) {
        // parity workspace for this step
        float* wsp   = swb + (t & 1) * PSTRIDE;
        float* sPU   = wsp;          // 64: P_u, row stride 8
        float* sF    = wsp + 64;     // 96: F, row stride 12
        float* sHP   = wsp + 160;    // 16: (hp0,hp1) interleaved per column
        float* sMU   = wsp + 176;    //  8: updated mean

        const float fr[4]  = {fh.x, fh.y, fh.z, fh.w};
        const float hao[4] = {hA.x, hA.y, hA.z, hA.w};
        const float hco[4] = {hC.x, hC.y, hC.z, hC.w};
        const float y0 = yv.x, y1 = yv.y;

        // prefetch next step (overlaps prev step's phase-3 tail: no barrier)
        {
            const float* Fn = Fb + (size_t)(t + 1) * 64;
            fh = *(const float4*)(Fn + i * 8 + cb);
            const float* Hn = Hb + (size_t)(t + 1) * 16;
            hA = *(const float4*)(Hn + cb);
            hC = *(const float4*)(Hn + 8 + cb);
            yv = *(const float2*)(yb + (size_t)(t + 1) * 2);
        }

        // ---- phase 1: F quarter to SMEM; HP column i via partial + shfl ----
        *(float4*)(sF + i * 12 + cb) = make_float4(fr[0], fr[1], fr[2], fr[3]);
        float hp0 = 0.f, hp1 = 0.f;
#pragma unroll
        for (int m = 0; m < 4; ++m) {      // P[s][i] = P[i][s] (symmetric)
            hp0 += hao[m] * pr[m];
            hp1 += hco[m] * pr[m];
        }
        hp0 += __shfl_xor_sync(FULL, hp0, 8);
        hp1 += __shfl_xor_sync(FULL, hp1, 8);
        if (c == 0) *(float2*)(sHP + 2 * i) = make_float2(hp0, hp1);
        __syncwarp();  // sync A: sF, sHP visible; prev-step sMean write ordered

        // ---- phase 2: Smat, gain, P_u quarter-row, mean_u ----
        float HP0o[4], HP1o[4];
        {
            const float4 u0 = *(const float4*)(sHP + 2 * cb);
            const float4 u1 = *(const float4*)(sHP + 2 * cb + 4);
            HP0o[0]=u0.x; HP1o[0]=u0.y; HP0o[1]=u0.z; HP1o[1]=u0.w;
            HP0o[2]=u1.x; HP1o[2]=u1.y; HP0o[3]=u1.z; HP1o[3]=u1.w;
        }
        float s00p = 0.f, s01p = 0.f, s10p = 0.f, s11p = 0.f;
#pragma unroll
        for (int m = 0; m < 4; ++m) {
            s00p += HP0o[m] * hao[m];
            s01p += HP0o[m] * hco[m];
            s10p += HP1o[m] * hao[m];
            s11p += HP1o[m] * hco[m];
        }
        const float s00 = R00 + s00p + __shfl_xor_sync(FULL, s00p, 8);
        const float s01 = R01 + s01p + __shfl_xor_sync(FULL, s01p, 8);
        const float s10 = R10 + s10p + __shfl_xor_sync(FULL, s10p, 8);
        const float s11 = R11 + s11p + __shfl_xor_sync(FULL, s11p, 8);
        const float inv = 1.0f / (s00 * s11 - s01 * s10);
        const float w0i = inv * ( s11 * hp0 - s01 * hp1);
        const float w1i = inv * (-s10 * hp0 + s00 * hp1);

        // P_u quarter-row
        float pu[4];
#pragma unroll
        for (int m = 0; m < 4; ++m)
            pu[m] = pr[m] - w0i * HP0o[m] - w1i * HP1o[m];
        *(float4*)(sPU + i * 8 + cb) = make_float4(pu[0], pu[1], pu[2], pu[3]);

        // residual via own-half partials + shfl (sMean: written phase3(t-1),
        // ordered by sync A above)
        {
            const float4 mo = *(const float4*)(sMn + cb);
            float r0p = hao[0]*mo.x + hao[1]*mo.y + hao[2]*mo.z + hao[3]*mo.w;
            float r1p = hco[0]*mo.x + hco[1]*mo.y + hco[2]*mo.z + hco[3]*mo.w;
            const float r0 = y0 - (r0p + __shfl_xor_sync(FULL, r0p, 8));
            const float r1 = y1 - (r1p + __shfl_xor_sync(FULL, r1p, 8));
            if (c == 0) sMU[i] = sMn[i] + w0i * r0 + w1i * r1;
        }
        __syncwarp();  // sync B: sPU, sMU visible; all sMean reads done

        // ---- phase 3: predict ----
        // mean predict FIRST (hoists its LDS/shfl under the G matmul; sMean
        // store lands early, covered by next step's sync A)
        {
            const float4 muo = *(const float4*)(sMU + cb);
            float mpp = fr[0]*muo.x + fr[1]*muo.y + fr[2]*muo.z + fr[3]*muo.w;
            const float mp = mpp + __shfl_xor_sync(FULL, mpp, 8);
            if (c == 0) {
                sMn[i] = mp;
                omb[(size_t)(t + 1) * 8 + i] = mp;
            }
        }

        // other quarter of own F row from partner lane
        float fo[4];
#pragma unroll
        for (int m = 0; m < 4; ++m)
            fo[m] = __shfl_xor_sync(FULL, fr[m], 8);

        // G[i][own cols] = sum_j F[i][j] * Pu[j][own cols]
        float g0 = 0.f, g1 = 0.f, g2 = 0.f, g3 = 0.f;
#pragma unroll
        for (int m = 0; m < 4; ++m) {   // j in own half, coeff fr[m]
            const float4 pj = *(const float4*)(sPU + (cb + m) * 8 + cb);
            g0 += fr[m] * pj.x; g1 += fr[m] * pj.y;
            g2 += fr[m] * pj.z; g3 += fr[m] * pj.w;
        }
#pragma unroll
        for (int m = 0; m < 4; ++m) {   // j in other half, coeff fo[m]
            const float4 pj = *(const float4*)(sPU + (ob + m) * 8 + cb);
            g0 += fo[m] * pj.x; g1 += fo[m] * pj.y;
            g2 += fo[m] * pj.z; g3 += fo[m] * pj.w;
        }
        // partner's G row half: rx[m] = G[i][ob+m]
        const float rx0 = __shfl_xor_sync(FULL, g0, 8);
        const float rx1 = __shfl_xor_sync(FULL, g1, 8);
        const float rx2 = __shfl_xor_sync(FULL, g2, 8);
        const float rx3 = __shfl_xor_sync(FULL, g3, 8);

        // P'[i][cb+kk] = G_row . F[k][:] + Q   (direct-offset F reads)
        float pn[4];
#pragma unroll
        for (int kk = 0; kk < 4; ++kk) {
            const int k = cb + kk;
            const float4 qo = *(const float4*)(sF + k * 12 + cb);  // F[k][own]
            const float4 qt = *(const float4*)(sF + k * 12 + ob);  // F[k][other]
            pn[kk] = Qr[kk]
                   + g0*qo.x + g1*qo.y + g2*qo.z + g3*qo.w
                   + rx0*qt.x + rx1*qt.y + rx2*qt.z + rx3*qt.w;
        }
#pragma unroll
        for (int m = 0; m < 4; ++m) pr[m] = pn[m];

        *(float4*)(ocb + (size_t)(t + 1) * 64 + i * 8 + cb) =
            make_float4(pn[0], pn[1], pn[2], pn[3]);
        // NO sync here: next step writes the OTHER parity buffer; sMean RAW is
        // ordered by next step's sync A; WAR on this buffer is 2 barriers deep.
    }
}

extern "C" void kernel_launch(void* const* d_in, const int* in_sizes, int n_in,
                              void* d_out, int out_size)
{
    // metadata order: y, F, H, Q, R, init_mean, init_cov, n_step
    const float* gy     = (const float*)d_in[0];
    const float* gF     = (const float*)d_in[1];
    const float* gH     = (const float*)d_in[2];
    const float* gQ     = (const float*)d_in[3];
    const float* gR     = (const float*)d_in[4];
    const float* gMean0 = (const float*)d_in[5];
    const float* gCov0  = (const float*)d_in[6];
    (void)in_sizes; (void)n_in;

    float* oMean = (float*)d_out;                          // [B,T,8]
    float* oCov  = (float*)d_out + (size_t)Bb * Tt * 8;    // [B,T,8,8]
    (void)out_size;

    kalman_kernel<<<Bb / 2, 32>>>(gy, gF, gH, gQ, gR, gMean0, gCov0,
                                  oMean, oCov);
}

// round 16
// speedup vs baseline: 1.7227x; 1.0354x over previous
#include <cuda_runtime.h>

// Kalman filter, simple-form update, select-free column-split layout.
// Exact 163.9us round-10 kernel with ONE subtractive delta:
//   HP is gathered in phase 2 via 8 index-mode shuffles from the registers
//   where phase 1 already reduced it, instead of an STS -> syncwarp -> LDS
//   round trip. sync A is deleted (3 -> 2 syncs per step); sync B still
//   orders sF/sPU/sMU stores before their phase-3 reads, and the end-of-step
//   sync still covers the sMean RAW and the sF/sPU WAR, as in round 10.
// B=4096, T=200, S=8, M=2.
// 16 lanes/batch: lane (i = row, c = column half) owns P[i][4c..4c+3].
// 2 batches per 32-thread warp, 2048 warps (~3.46/SMSP).

namespace {
constexpr int Bb  = 4096;
constexpr int Tt  = 200;
constexpr int WSF = 208;   // per-batch workspace stride in floats
constexpr unsigned FULL = 0xffffffffu;
}

__global__ __launch_bounds__(32)
void kalman_kernel(const float* __restrict__ gy,      // [B,T,2]
                   const float* __restrict__ gF,      // [B,T,8,8]
                   const float* __restrict__ gH,      // [B,T,2,8]
                   const float* __restrict__ gQ,      // [8,8]
                   const float* __restrict__ gR,      // [2,2]
                   const float* __restrict__ gMean0,  // [B,8]
                   const float* __restrict__ gCov0,   // [8,8]
                   float* __restrict__ oMean,         // [B,T,8]
                   float* __restrict__ oCov)          // [B,T,8,8]
{
    __shared__ __align__(16) float sw[2 * WSF];
    const int lane = threadIdx.x;
    const int lb   = lane >> 4;          // batch within warp
    const int i    = lane & 7;           // state row
    const int c    = (lane >> 3) & 1;    // column half
    const int cb   = 4 * c;              // own column base
    const int ob   = 4 - cb;             // other column base
    const int b    = blockIdx.x * 2 + lb;
    const int gsrc = (lane & 16) | cb;   // shfl source base for HP gather

    float* wsp   = sw + lb * WSF;
    float* sPU   = wsp;          // 64: P_u, row stride 8
    float* sF    = wsp + 64;     // 96: F, row stride 12
    float* sMU   = wsp + 176;    //  8: updated mean
    float* sMean = wsp + 184;    //  8: predicted mean

    const float R00 = gR[0], R01 = gR[1], R10 = gR[2], R11 = gR[3];
    float Qr[4];
#pragma unroll
    for (int m = 0; m < 4; ++m) Qr[m] = gQ[i * 8 + cb + m];

    float* omb = oMean + (size_t)b * Tt * 8;
    float* ocb = oCov  + (size_t)b * Tt * 64;

    // ---- init: own quarter-row of P; t=0 outputs ----
    float pr[4];
    {
        const float4 p0 = *(const float4*)(gCov0 + i * 8 + cb);
        pr[0]=p0.x; pr[1]=p0.y; pr[2]=p0.z; pr[3]=p0.w;
        *(float4*)(ocb + i * 8 + cb) = p0;
    }
    if (c == 0) {
        const float m0 = gMean0[b * 8 + i];
        sMean[i] = m0;
        omb[i]   = m0;
    }

    const float* Fb = gF + (size_t)b * Tt * 64;
    const float* Hb = gH + (size_t)b * Tt * 16;
    const float* yb = gy + (size_t)b * Tt * 2;

    // ---- prefetch step 0: own quarters only ----
    float4 fh = *(const float4*)(Fb + i * 8 + cb);   // F[i][cb..cb+3]
    float4 hA = *(const float4*)(Hb + cb);           // H[0][cb..cb+3]
    float4 hC = *(const float4*)(Hb + 8 + cb);       // H[1][cb..cb+3]
    float2 yv = *(const float2*)(yb);

    __syncwarp();

    for (int t = 0; t < Tt - 1; ++t) {
        const float fr[4]  = {fh.x, fh.y, fh.z, fh.w};
        const float hao[4] = {hA.x, hA.y, hA.z, hA.w};
        const float hco[4] = {hC.x, hC.y, hC.z, hC.w};
        const float y0 = yv.x, y1 = yv.y;

        // prefetch next step
        {
            const float* Fn = Fb + (size_t)(t + 1) * 64;
            fh = *(const float4*)(Fn + i * 8 + cb);
            const float* Hn = Hb + (size_t)(t + 1) * 16;
            hA = *(const float4*)(Hn + cb);
            hC = *(const float4*)(Hn + 8 + cb);
            yv = *(const float2*)(yb + (size_t)(t + 1) * 2);
        }

        // ---- phase 1: F quarter to SMEM; HP column i via partial + shfl ----
        *(float4*)(sF + i * 12 + cb) = make_float4(fr[0], fr[1], fr[2], fr[3]);
        float hp0 = 0.f, hp1 = 0.f;
#pragma unroll
        for (int m = 0; m < 4; ++m) {      // P[s][i] = P[i][s] (symmetric)
            hp0 += hao[m] * pr[m];
            hp1 += hco[m] * pr[m];
        }
        hp0 += __shfl_xor_sync(FULL, hp0, 8);
        hp1 += __shfl_xor_sync(FULL, hp1, 8);
        // (no sHP store, no sync A: HP lives in registers, gathered below)

        // ---- phase 2: Smat, gain, P_u quarter-row, mean_u ----
        // own-half HP columns via index shuffles (source lane = (lb*16)|(cb+m))
        float HP0o[4], HP1o[4];
#pragma unroll
        for (int m = 0; m < 4; ++m) {
            HP0o[m] = __shfl_sync(FULL, hp0, gsrc + m);
            HP1o[m] = __shfl_sync(FULL, hp1, gsrc + m);
        }
        float s00p = 0.f, s01p = 0.f, s10p = 0.f, s11p = 0.f;
#pragma unroll
        for (int m = 0; m < 4; ++m) {
            s00p += HP0o[m] * hao[m];
            s01p += HP0o[m] * hco[m];
            s10p += HP1o[m] * hao[m];
            s11p += HP1o[m] * hco[m];
        }
        const float s00 = R00 + s00p + __shfl_xor_sync(FULL, s00p, 8);
        const float s01 = R01 + s01p + __shfl_xor_sync(FULL, s01p, 8);
        const float s10 = R10 + s10p + __shfl_xor_sync(FULL, s10p, 8);
        const float s11 = R11 + s11p + __shfl_xor_sync(FULL, s11p, 8);
        const float inv = 1.0f / (s00 * s11 - s01 * s10);
        const float w0i = inv * ( s11 * hp0 - s01 * hp1);
        const float w1i = inv * (-s10 * hp0 + s00 * hp1);

        // P_u quarter-row
        float pu[4];
#pragma unroll
        for (int m = 0; m < 4; ++m)
            pu[m] = pr[m] - w0i * HP0o[m] - w1i * HP1o[m];
        *(float4*)(sPU + i * 8 + cb) = make_float4(pu[0], pu[1], pu[2], pu[3]);

        // residual via own-half partials + shfl (sMean written phase 3 of the
        // previous step; ordered by the end-of-step sync)
        {
            const float4 mo = *(const float4*)(sMean + cb);
            float r0p = hao[0]*mo.x + hao[1]*mo.y + hao[2]*mo.z + hao[3]*mo.w;
            float r1p = hco[0]*mo.x + hco[1]*mo.y + hco[2]*mo.z + hco[3]*mo.w;
            const float r0 = y0 - (r0p + __shfl_xor_sync(FULL, r0p, 8));
            const float r1 = y1 - (r1p + __shfl_xor_sync(FULL, r1p, 8));
            if (c == 0) sMU[i] = sMean[i] + w0i * r0 + w1i * r1;
        }
        __syncwarp();  // sync B: sF, sPU, sMU visible; all sMean reads done

        // ---- phase 3: predict ----
        // other quarter of own F row from partner lane
        float fo[4];
#pragma unroll
        for (int m = 0; m < 4; ++m)
            fo[m] = __shfl_xor_sync(FULL, fr[m], 8);

        // G[i][own cols] = sum_j F[i][j] * Pu[j][own cols]
        float g0 = 0.f, g1 = 0.f, g2 = 0.f, g3 = 0.f;
#pragma unroll
        for (int m = 0; m < 4; ++m) {   // j in own half, coeff fr[m]
            const float4 pj = *(const float4*)(sPU + (cb + m) * 8 + cb);
            g0 += fr[m] * pj.x; g1 += fr[m] * pj.y;
            g2 += fr[m] * pj.z; g3 += fr[m] * pj.w;
        }
#pragma unroll
        for (int m = 0; m < 4; ++m) {   // j in other half, coeff fo[m]
            const float4 pj = *(const float4*)(sPU + (ob + m) * 8 + cb);
            g0 += fo[m] * pj.x; g1 += fo[m] * pj.y;
            g2 += fo[m] * pj.z; g3 += fo[m] * pj.w;
        }
        // partner's G row half: rx[m] = G[i][ob+m]
        const float rx0 = __shfl_xor_sync(FULL, g0, 8);
        const float rx1 = __shfl_xor_sync(FULL, g1, 8);
        const float rx2 = __shfl_xor_sync(FULL, g2, 8);
        const float rx3 = __shfl_xor_sync(FULL, g3, 8);

        // P'[i][cb+kk] = G_row . F[k][:] + Q   (direct-offset F reads)
        float pn[4];
#pragma unroll
        for (int kk = 0; kk < 4; ++kk) {
            const int k = cb + kk;
            const float4 qo = *(const float4*)(sF + k * 12 + cb);  // F[k][own]
            const float4 qt = *(const float4*)(sF + k * 12 + ob);  // F[k][other]
            pn[kk] = Qr[kk]
                   + g0*qo.x + g1*qo.y + g2*qo.z + g3*qo.w
                   + rx0*qt.x + rx1*qt.y + rx2*qt.z + rx3*qt.w;
        }
#pragma unroll
        for (int m = 0; m < 4; ++m) pr[m] = pn[m];

        *(float4*)(ocb + (size_t)(t + 1) * 64 + i * 8 + cb) =
            make_float4(pn[0], pn[1], pn[2], pn[3]);

        // mean predict: own-half partial + shfl
        {
            const float4 muo = *(const float4*)(sMU + cb);
            float mpp = fr[0]*muo.x + fr[1]*muo.y + fr[2]*muo.z + fr[3]*muo.w;
            const float mp = mpp + __shfl_xor_sync(FULL, mpp, 8);
            if (c == 0) {
                sMean[i] = mp;   // old-sMean reads all ended before sync B
                omb[(size_t)(t + 1) * 8 + i] = mp;
            }
        }
        __syncwarp();  // end-of-step sync: phase-3 sF/sPU reads done (WAR),
                       // sMean visible for next iteration (RAW)
    }
}

extern "C" void kernel_launch(void* const* d_in, const int* in_sizes, int n_in,
                              void* d_out, int out_size)
{
    // metadata order: y, F, H, Q, R, init_mean, init_cov, n_step
    const float* gy     = (const float*)d_in[0];
    const float* gF     = (const float*)d_in[1];
    const float* gH     = (const float*)d_in[2];
    const float* gQ     = (const float*)d_in[3];
    const float* gR     = (const float*)d_in[4];
    const float* gMean0 = (const float*)d_in[5];
    const float* gCov0  = (const float*)d_in[6];
    (void)in_sizes; (void)n_in;

    float* oMean = (float*)d_out;                          // [B,T,8]
    float* oCov  = (float*)d_out + (size_t)Bb * Tt * 8;    // [B,T,8,8]
    (void)out_size;

    kalman_kernel<<<Bb / 2, 32>>>(gy, gF, gH, gQ, gR, gMean0, gCov0,
                                  oMean, oCov);
}